// round 5
// baseline (speedup 1.0000x reference)
#include <cuda_runtime.h>

#define TT   512
#define BB   64
#define HH   512
#define G4   2048
#define MS   300
#define INW  812
#define NBLK 128

// ---------------- device scratch ----------------
__device__ float d_Xp[2][TT * BB][G4];      // x-projection + biases (537 MB)
__device__ float d_hbuf[2][2][BB][HH];      // [dir][parity][b][h]
__device__ float d_expl[2][MS][BB];         // unnormalized exp(logits), slot-major
__device__ float d_mem[2][BB][MS];
__device__ unsigned d_barcnt;

__global__ void reset_kernel() { d_barcnt = 0u; }

// ---------------- precompute: Xp = x @ Wx^T + b_ih + b_hh ----------------
__global__ void __launch_bounds__(256, 2) xproj_kernel(
    const float* __restrict__ seqs,
    const float* __restrict__ Wih_f, const float* __restrict__ Wih_b,
    const float* __restrict__ bih_f, const float* __restrict__ bhh_f,
    const float* __restrict__ bih_b, const float* __restrict__ bhh_b)
{
    const int d = blockIdx.z;
    const float* W  = d ? Wih_b : Wih_f;
    const float* bi = d ? bih_b : bih_f;
    const float* bh = d ? bhh_b : bhh_f;
    const int n0 = blockIdx.x * 128;
    const int m0 = blockIdx.y * 128;

    __shared__ float As[8][136];
    __shared__ float Bs[8][136];

    const int tid  = threadIdx.x;
    const int lrow = tid >> 1;
    const int kseg = (tid & 1) * 4;

    const int grow = m0 + lrow;
    const int tt   = grow >> 6;
    const int bb   = grow & 63;
    const int tsrc = d ? (TT - 1 - tt) : tt;
    const float* aptr = seqs + ((size_t)bb * TT + tsrc) * HH + kseg;
    const float* bptr = W + (size_t)(n0 + lrow) * INW + kseg;

    float acc[8][8];
#pragma unroll
    for (int r = 0; r < 8; ++r)
#pragma unroll
        for (int c = 0; c < 8; ++c) acc[r][c] = 0.0f;

    const int ty = tid >> 4;
    const int tx = tid & 15;

    for (int k0 = 0; k0 < 512; k0 += 8) {
        float4 av = *(const float4*)(aptr + k0);
        float4 bv = *(const float4*)(bptr + k0);
        __syncthreads();
        As[kseg + 0][lrow] = av.x; As[kseg + 1][lrow] = av.y;
        As[kseg + 2][lrow] = av.z; As[kseg + 3][lrow] = av.w;
        Bs[kseg + 0][lrow] = bv.x; Bs[kseg + 1][lrow] = bv.y;
        Bs[kseg + 2][lrow] = bv.z; Bs[kseg + 3][lrow] = bv.w;
        __syncthreads();
#pragma unroll
        for (int kk = 0; kk < 8; ++kk) {
            float a[8], b[8];
            *(float4*)&a[0] = *(const float4*)&As[kk][ty * 8];
            *(float4*)&a[4] = *(const float4*)&As[kk][ty * 8 + 4];
            *(float4*)&b[0] = *(const float4*)&Bs[kk][tx * 8];
            *(float4*)&b[4] = *(const float4*)&Bs[kk][tx * 8 + 4];
#pragma unroll
            for (int r = 0; r < 8; ++r)
#pragma unroll
                for (int c = 0; c < 8; ++c) acc[r][c] += a[r] * b[c];
        }
    }

    float bias[8];
#pragma unroll
    for (int c = 0; c < 8; ++c) {
        int col = n0 + tx * 8 + c;
        bias[c] = bi[col] + bh[col];
    }
#pragma unroll
    for (int r = 0; r < 8; ++r) {
        float* dst = &d_Xp[d][m0 + ty * 8 + r][n0 + tx * 8];
#pragma unroll
        for (int c = 0; c < 8; ++c) dst[c] = acc[r][c] + bias[c];
    }
}

// ---------------- grid barrier (nanosleep backoff spin) ----------------
__device__ __forceinline__ void gridbar() {
    __threadfence();
    __syncthreads();
    if (threadIdx.x == 0) {
        unsigned t = atomicAdd(&d_barcnt, 1u);
        unsigned target = (t / NBLK + 1u) * NBLK;
        while (*(volatile unsigned*)&d_barcnt < target) {
            __nanosleep(64);
        }
    }
    __syncthreads();
    __threadfence();
}

// ---------------- persistent recurrence ----------------
__global__ void __launch_bounds__(256, 1) rnn_persist(
    const float* __restrict__ Whh_f, const float* __restrict__ Whh_b,
    const float* __restrict__ Wih_f, const float* __restrict__ Wih_b,
    const float* __restrict__ Mk_f,  const float* __restrict__ Mk_b,
    const float* __restrict__ Mv_f,  const float* __restrict__ Mv_b,
    const int* __restrict__ lens,
    float* __restrict__ out)
{
    extern __shared__ float expl_s[];       // [300][68]  81600 B
    __shared__ float c_s[512];
    __shared__ float S_s[64];
    __shared__ float g_s[64 * 36];
    __shared__ float inp_s[16 * 68];
    __shared__ float w_s[16 * 36];

    const int blk = blockIdx.x;
    const int d   = blk >> 6;
    const int j   = blk & 63;
    const float* Whh = d ? Whh_b : Whh_f;
    const float* Wih = d ? Wih_b : Wih_f;
    const float* Mk  = d ? Mk_b : Mk_f;
    const float* Mv  = d ? Mv_b : Mv_f;

    const int tid  = threadIdx.x;
    const int w    = tid >> 5;
    const int lane = tid & 31;
    const int ty   = tid >> 5;
    const int tx   = tid & 31;
    const int gate = tx >> 3;
    const int u    = tx & 7;

    const int s0 = (j * MS) >> 6, s1 = ((j + 1) * MS) >> 6;
    const int m0 = s0, m1 = s1;

    for (int i = tid; i < 512; i += 256) c_s[i] = 0.0f;
    __syncthreads();

    for (int t = 0; t < TT; ++t) {
        const int rp = t & 1, wp = rp ^ 1;

        if (t > 0) {
            // ---- Phase A: expl[s][b] = exp(h[b] . Mk[s]) ----
            if (w < s1 - s0) {
                int s = s0 + w;
                const float4* mk = (const float4*)(Mk + (size_t)s * HH);
                float4 mv0 = mk[lane], mv1 = mk[lane + 32];
                float4 mv2 = mk[lane + 64], mv3 = mk[lane + 96];
                const float* hb = &d_hbuf[d][rp][0][0];
                for (int b = 0; b < BB; ++b) {
                    const float4* hr = (const float4*)(hb + (size_t)b * HH);
                    float4 h0 = __ldcg(hr + lane), h1 = __ldcg(hr + lane + 32);
                    float4 h2 = __ldcg(hr + lane + 64), h3 = __ldcg(hr + lane + 96);
                    float p = h0.x*mv0.x + h0.y*mv0.y + h0.z*mv0.z + h0.w*mv0.w
                            + h1.x*mv1.x + h1.y*mv1.y + h1.z*mv1.z + h1.w*mv1.w
                            + h2.x*mv2.x + h2.y*mv2.y + h2.z*mv2.z + h2.w*mv2.w
                            + h3.x*mv3.x + h3.y*mv3.y + h3.z*mv3.z + h3.w*mv3.w;
                    p += __shfl_xor_sync(0xffffffffu, p, 16);
                    p += __shfl_xor_sync(0xffffffffu, p, 8);
                    p += __shfl_xor_sync(0xffffffffu, p, 4);
                    p += __shfl_xor_sync(0xffffffffu, p, 2);
                    p += __shfl_xor_sync(0xffffffffu, p, 1);
                    if (lane == 0) d_expl[d][s][b] = __expf(p);
                }
            }
            gridbar();

            // ---- Phase B: softmax-normalize + mem = alpha @ Mv^T ----
            for (int idx = tid; idx < MS * BB; idx += 256) {
                int s = idx >> 6, b = idx & 63;
                expl_s[s * 68 + b] = __ldcg(&d_expl[d][s][b]);
            }
            __syncthreads();
            {
                int b = tid >> 2, q = tid & 3;
                float ps = 0.0f;
                for (int s = q * 75; s < q * 75 + 75; ++s) ps += expl_s[s * 68 + b];
                ps += __shfl_xor_sync(0xffffffffu, ps, 1);
                ps += __shfl_xor_sync(0xffffffffu, ps, 2);
                if (q == 0) S_s[b] = ps;
            }
            __syncthreads();
            {
                int b = tid >> 2, q = tid & 3;
                for (int m = m0; m < m1; ++m) {
                    const float* mvrow = Mv + (size_t)m * MS;
                    float acc = 0.0f;
                    for (int s = q * 75; s < q * 75 + 75; ++s)
                        acc += expl_s[s * 68 + b] * __ldg(mvrow + s);
                    acc += __shfl_xor_sync(0xffffffffu, acc, 1);
                    acc += __shfl_xor_sync(0xffffffffu, acc, 2);
                    if (q == 0) d_mem[d][b][m] = acc / S_s[b];
                }
            }
            gridbar();
        }

        // ---- Phase D: gates = Xp + mem@Wm^T + h@Whh^T ; cell ----
        float acc[8];
        {
            const float* xp = &d_Xp[d][(size_t)t * BB][0];
            const int col = gate * 512 + j * 8 + u;
#pragma unroll
            for (int r = 0; r < 8; ++r)
                acc[r] = __ldcs(xp + (size_t)(ty * 8 + r) * G4 + col);
        }

        if (t > 0) {
            // mem part: K = 300
            const float* inp = &d_mem[d][0][0];
            for (int k0 = 0; k0 < MS; k0 += 16) {
                __syncthreads();
                {
                    int kk = tid & 15, k = k0 + kk;
#pragma unroll
                    for (int i = 0; i < 4; ++i) {
                        int b = (tid >> 4) + i * 16;
                        inp_s[kk * 68 + b] = (k < MS) ? __ldcg(inp + (size_t)b * MS + k) : 0.0f;
                    }
#pragma unroll
                    for (int i = 0; i < 2; ++i) {
                        int x = (tid >> 4) + i * 16;
                        int row = (x >> 3) * 512 + j * 8 + (x & 7);
                        w_s[kk * 36 + x] = (k < MS) ? __ldg(Wih + (size_t)row * INW + 512 + k) : 0.0f;
                    }
                }
                __syncthreads();
#pragma unroll
                for (int kk = 0; kk < 16; ++kk) {
                    float wv = w_s[kk * 36 + tx];
                    float4 a0 = *(const float4*)&inp_s[kk * 68 + ty * 8];
                    float4 a1 = *(const float4*)&inp_s[kk * 68 + ty * 8 + 4];
                    acc[0] += a0.x * wv; acc[1] += a0.y * wv;
                    acc[2] += a0.z * wv; acc[3] += a0.w * wv;
                    acc[4] += a1.x * wv; acc[5] += a1.y * wv;
                    acc[6] += a1.z * wv; acc[7] += a1.w * wv;
                }
            }
            // h part: K = 512
            const float* inp2 = &d_hbuf[d][rp][0][0];
            for (int k0 = 0; k0 < HH; k0 += 16) {
                __syncthreads();
                {
                    int kk = tid & 15, k = k0 + kk;
#pragma unroll
                    for (int i = 0; i < 4; ++i) {
                        int b = (tid >> 4) + i * 16;
                        inp_s[kk * 68 + b] = __ldcg(inp2 + (size_t)b * HH + k);
                    }
#pragma unroll
                    for (int i = 0; i < 2; ++i) {
                        int x = (tid >> 4) + i * 16;
                        int row = (x >> 3) * 512 + j * 8 + (x & 7);
                        w_s[kk * 36 + x] = __ldg(Whh + (size_t)row * HH + k);
                    }
                }
                __syncthreads();
#pragma unroll
                for (int kk = 0; kk < 16; ++kk) {
                    float wv = w_s[kk * 36 + tx];
                    float4 a0 = *(const float4*)&inp_s[kk * 68 + ty * 8];
                    float4 a1 = *(const float4*)&inp_s[kk * 68 + ty * 8 + 4];
                    acc[0] += a0.x * wv; acc[1] += a0.y * wv;
                    acc[2] += a0.z * wv; acc[3] += a0.w * wv;
                    acc[4] += a1.x * wv; acc[5] += a1.y * wv;
                    acc[6] += a1.z * wv; acc[7] += a1.w * wv;
                }
            }
        }

        __syncthreads();
#pragma unroll
        for (int r = 0; r < 8; ++r) g_s[(ty * 8 + r) * 36 + tx] = acc[r];
        __syncthreads();

#pragma unroll
        for (int pi = 0; pi < 2; ++pi) {
            int p = tid + pi * 256;
            int b = p >> 3, uu = p & 7;
            float gi = g_s[b * 36 + uu];
            float gf = g_s[b * 36 + 8 + uu];
            float gg = g_s[b * 36 + 16 + uu];
            float go = g_s[b * 36 + 24 + uu];
            float iv = 1.0f / (1.0f + __expf(-gi));
            float fv = 1.0f / (1.0f + __expf(-gf));
            float gv = tanhf(gg);
            float ov = 1.0f / (1.0f + __expf(-go));
            float c = fv * c_s[p] + iv * gv;
            c_s[p] = c;
            float h = ov * tanhf(c);
            d_hbuf[d][wp][b][j * 8 + uu] = h;
            int torig = d ? (TT - 1 - t) : t;
            float mval = (torig < lens[b]) ? h : 0.0f;
            out[((size_t)b * TT + torig) * 1024 + d * 512 + j * 8 + uu] = mval;
        }
        gridbar();
    }
}

// ---------------- launch ----------------
extern "C" void kernel_launch(void* const* d_in, const int* in_sizes, int n_in,
                              void* d_out, int out_size) {
    const float* seqs   = (const float*)d_in[0];
    const int*   ln     = (const int*)d_in[1];     // int32 (JAX x64 disabled)
    const float* Wih_f  = (const float*)d_in[2];
    const float* Whh_f  = (const float*)d_in[3];
    const float* bih_f  = (const float*)d_in[4];
    const float* bhh_f  = (const float*)d_in[5];
    const float* Mk_f   = (const float*)d_in[6];
    const float* Mv_f   = (const float*)d_in[7];
    const float* Wih_b  = (const float*)d_in[8];
    const float* Whh_b  = (const float*)d_in[9];
    const float* bih_b  = (const float*)d_in[10];
    const float* bhh_b  = (const float*)d_in[11];
    const float* Mk_b   = (const float*)d_in[12];
    const float* Mv_b   = (const float*)d_in[13];
    float* out = (float*)d_out;

    cudaFuncSetAttribute(rnn_persist,
                         cudaFuncAttributeMaxDynamicSharedMemorySize, 81600);

    reset_kernel<<<1, 1>>>();
    xproj_kernel<<<dim3(16, 256, 2), 256>>>(seqs, Wih_f, Wih_b,
                                            bih_f, bhh_f, bih_b, bhh_b);
    rnn_persist<<<NBLK, 256, 81600>>>(Whh_f, Whh_b, Wih_f, Wih_b,
                                      Mk_f, Mk_b, Mv_f, Mv_b, ln, out);
}